// round 15
// baseline (speedup 1.0000x reference)
#include <cuda_runtime.h>
#include <cstdint>

// ---------------------------------------------------------------------------
// QuantLinear: y[M,N] = x[M,K] * W[N,K]^T, W dequantized from Q4_K-like format.
// M = 4096, K = 4096, N = 4096, fp32 in/out.
//
// The harness ptxas pass targets sm_103 (no 'a'), so tcgen05 is unavailable.
// Plan: pre-round x and dequantized W to tf32 (cvt.rna = unbiased), then a
// portable mma.sync m16n8k8 tf32 GEMM with a 4-stage cp.async pipeline and
// XOR-swizzled shared memory. fp32 accumulation in registers.
// ---------------------------------------------------------------------------

static constexpr int MDIM = 4096;
static constexpr int NDIM = 4096;
static constexpr int KDIM = 4096;

static constexpr int BM = 128;
static constexpr int BN = 128;
static constexpr int BK = 32;
static constexpr int STAGES = 4;
static constexpr int KTILES = KDIM / BK;          // 128

static constexpr int TILE_FLOATS = BM * BK;       // 4096 floats = 16 KB
static constexpr int STAGE_FLOATS = 2 * TILE_FLOATS;
static constexpr int SMEM_BYTES = STAGES * STAGE_FLOATS * 4;  // 131072

// Scratch (device-global: no runtime allocation allowed)
__device__ float g_xr[(size_t)MDIM * KDIM];  // 64 MB tf32-rounded activations
__device__ float g_w [(size_t)NDIM * KDIM];  // 64 MB tf32-rounded weights [N][K]

// ---------------------------------------------------------------------------
// helpers
// ---------------------------------------------------------------------------
__device__ __forceinline__ float to_tf32(float v) {
    uint32_t t;
    asm("cvt.rna.tf32.f32 %0, %1;" : "=r"(t) : "f"(v));
    return __uint_as_float(t);
}

__device__ __forceinline__ uint32_t smem_u32(const void* p) {
    uint32_t a;
    asm("{ .reg .u64 t; cvta.to.shared.u64 t, %1; cvt.u32.u64 %0, t; }" : "=r"(a) : "l"(p));
    return a;
}

__device__ __forceinline__ void cp_async16(uint32_t smem_dst, const void* gmem_src) {
    asm volatile("cp.async.cg.shared.global [%0], [%1], 16;"
                 :: "r"(smem_dst), "l"(gmem_src) : "memory");
}

__device__ __forceinline__ void mma_tf32(float* c, uint32_t a0, uint32_t a1,
                                         uint32_t a2, uint32_t a3,
                                         uint32_t b0, uint32_t b1) {
    asm volatile(
        "mma.sync.aligned.m16n8k8.row.col.f32.tf32.tf32.f32 "
        "{%0,%1,%2,%3}, {%4,%5,%6,%7}, {%8,%9}, {%0,%1,%2,%3};"
        : "+f"(c[0]), "+f"(c[1]), "+f"(c[2]), "+f"(c[3])
        : "r"(a0), "r"(a1), "r"(a2), "r"(a3), "r"(b0), "r"(b1));
}

// swizzled float index within one [rows][32] tile: k column XORed per row
__device__ __forceinline__ int sw_idx(int row, int k) {
    return row * BK + (k ^ ((row & 7) << 2));
}

// ---------------------------------------------------------------------------
// Kernel 1: round activations to tf32 (unbiased; removes truncation bias)
// ---------------------------------------------------------------------------
__global__ void __launch_bounds__(256) roundx_kernel(const float4* __restrict__ x) {
    int i = blockIdx.x * blockDim.x + threadIdx.x;
    float4 v = x[i];
    v.x = to_tf32(v.x); v.y = to_tf32(v.y); v.z = to_tf32(v.z); v.w = to_tf32(v.w);
    reinterpret_cast<float4*>(g_xr)[i] = v;
}

// ---------------------------------------------------------------------------
// Kernel 2: Q4_K dequantize -> g_w [N][K] row-major (K-major), tf32-rounded.
//   j even -> low nibble of packed[j/2], j odd -> high nibble.
//   super = j>>8, sub = (j>>5)&7
//   w = (q/15 * scales/63 + mins/63) * d + dmin
// ---------------------------------------------------------------------------
__global__ void __launch_bounds__(256) dequant_kernel(
    const int* __restrict__ packed, const float* __restrict__ d,
    const float* __restrict__ dmin, const int* __restrict__ scales,
    const int* __restrict__ mins) {
    int p = blockIdx.x * blockDim.x + threadIdx.x;   // 0 .. NUMEL/2-1
    int q = packed[p];
    int j = p << 1;
    int sup = j >> 8;
    int sbi = (sup << 3) + ((j >> 5) & 7);
    float sc = (float)scales[sbi] * (1.0f / 63.0f);
    float mn = (float)mins[sbi]   * (1.0f / 63.0f);
    float dd = d[sup];
    float dm = dmin[sup];
    float a = dd * sc * (1.0f / 15.0f);
    float b = mn * dd + dm;
    float w0 = (float)(q & 15)        * a + b;
    float w1 = (float)((q >> 4) & 15) * a + b;
    reinterpret_cast<float2*>(g_w)[p] = make_float2(to_tf32(w0), to_tf32(w1));
}

// ---------------------------------------------------------------------------
// Kernel 3: tf32 mma.sync GEMM, 128x128x32 CTA tile, 4-stage cp.async.
//   8 warps (2 M x 4 N), warp tile 64x32, m16n8k8 fragments, fp32 accum.
// ---------------------------------------------------------------------------
__global__ void __launch_bounds__(256, 1) gemm_tf32(float* __restrict__ out) {
    extern __shared__ float smem[];
    const uint32_t sbase = smem_u32(smem);

    const int tid   = threadIdx.x;
    const int wid   = tid >> 5;
    const int lane  = tid & 31;
    const int group = lane >> 2;      // 0..7
    const int tid4  = lane & 3;       // 0..3
    const int warpM = wid >> 2;       // 0..1
    const int warpN = wid & 3;        // 0..3

    const int tile_m = blockIdx.y * BM;
    const int tile_n = blockIdx.x * BN;

    // cp.async one K-stage. Thread t handles 4 x 16B chunks per tile:
    //   row = (t>>3) + {0,32,64,96}, k4 = (t&7)*4
    const int lrow = tid >> 3;              // 0..31
    const int k4   = (tid & 7) << 2;        // 0,4,...,28
    const int swk  = k4 ^ ((lrow & 7) << 2);  // same for rows lrow+32*i (row&7 invariant)

    auto load_stage = [&](int slot, int kt) {
        const int kb = kt * BK;
        const uint32_t sA = sbase + (uint32_t)(slot * STAGE_FLOATS) * 4u;
        const uint32_t sB = sA + (uint32_t)TILE_FLOATS * 4u;
        #pragma unroll
        for (int i = 0; i < 4; i++) {
            int row = lrow + i * 32;
            cp_async16(sA + (uint32_t)(row * BK + swk) * 4u,
                       &g_xr[(size_t)(tile_m + row) * KDIM + kb + k4]);
        }
        #pragma unroll
        for (int i = 0; i < 4; i++) {
            int row = lrow + i * 32;
            cp_async16(sB + (uint32_t)(row * BK + swk) * 4u,
                       &g_w[(size_t)(tile_n + row) * KDIM + kb + k4]);
        }
    };

    float acc[2][4][4];   // [m half? no: mfrag pairs] -> use [4][4][4] flattened below
    float accr[4][4][4];  // [mfrag][nfrag][reg]
    #pragma unroll
    for (int mf = 0; mf < 4; mf++)
        #pragma unroll
        for (int nf = 0; nf < 4; nf++)
            #pragma unroll
            for (int r = 0; r < 4; r++) accr[mf][nf][r] = 0.0f;
    (void)acc;

    // Prologue: fill STAGES-1 stages
    #pragma unroll
    for (int s = 0; s < STAGES - 1; s++) {
        load_stage(s, s);
        asm volatile("cp.async.commit_group;" ::: "memory");
    }

    const uint32_t* As_all = reinterpret_cast<const uint32_t*>(smem);

    #pragma unroll 1
    for (int i = 0; i < KTILES; i++) {
        asm volatile("cp.async.wait_group %0;" :: "n"(STAGES - 2) : "memory");
        __syncthreads();

        // Prefetch into the slot freed at iteration i-1
        if (i + STAGES - 1 < KTILES) {
            load_stage((i + STAGES - 1) & (STAGES - 1), i + STAGES - 1);
            asm volatile("cp.async.commit_group;" ::: "memory");
        }

        const int slot = i & (STAGES - 1);
        const uint32_t* As = As_all + slot * STAGE_FLOATS;
        const uint32_t* Bs = As + TILE_FLOATS;

        #pragma unroll
        for (int ks = 0; ks < BK / 8; ks++) {
            const int k0 = ks * 8 + tid4;
            uint32_t a[4][4];
            #pragma unroll
            for (int mf = 0; mf < 4; mf++) {
                int r0 = warpM * 64 + mf * 16 + group;
                a[mf][0] = As[sw_idx(r0,     k0)];
                a[mf][1] = As[sw_idx(r0 + 8, k0)];
                a[mf][2] = As[sw_idx(r0,     k0 + 4)];
                a[mf][3] = As[sw_idx(r0 + 8, k0 + 4)];
            }
            uint32_t b[4][2];
            #pragma unroll
            for (int nf = 0; nf < 4; nf++) {
                int n0 = warpN * 32 + nf * 8 + group;
                b[nf][0] = Bs[sw_idx(n0, k0)];
                b[nf][1] = Bs[sw_idx(n0, k0 + 4)];
            }
            #pragma unroll
            for (int mf = 0; mf < 4; mf++)
                #pragma unroll
                for (int nf = 0; nf < 4; nf++)
                    mma_tf32(accr[mf][nf], a[mf][0], a[mf][1], a[mf][2], a[mf][3],
                             b[nf][0], b[nf][1]);
        }
    }

    // Epilogue: direct fp32 stores (float2 per fragment half)
    #pragma unroll
    for (int mf = 0; mf < 4; mf++) {
        const int m0 = tile_m + warpM * 64 + mf * 16 + group;
        #pragma unroll
        for (int nf = 0; nf < 4; nf++) {
            const int n = tile_n + warpN * 32 + nf * 8 + tid4 * 2;
            float2 v0 = make_float2(accr[mf][nf][0], accr[mf][nf][1]);
            float2 v1 = make_float2(accr[mf][nf][2], accr[mf][nf][3]);
            *reinterpret_cast<float2*>(out + (size_t)m0 * NDIM + n) = v0;
            *reinterpret_cast<float2*>(out + (size_t)(m0 + 8) * NDIM + n) = v1;
        }
    }
}

// ---------------------------------------------------------------------------
// Launch
// ---------------------------------------------------------------------------
extern "C" void kernel_launch(void* const* d_in, const int* in_sizes, int n_in,
                              void* d_out, int out_size) {
    const float* x      = (const float*)d_in[0];
    const int*   packed = (const int*)  d_in[1];
    const float* d      = (const float*)d_in[2];
    const float* dmin   = (const float*)d_in[3];
    const int*   scales = (const int*)  d_in[4];
    const int*   mins   = (const int*)  d_in[5];
    float* out = (float*)d_out;

    cudaFuncSetAttribute(gemm_tf32, cudaFuncAttributeMaxDynamicSharedMemorySize,
                         SMEM_BYTES);

    roundx_kernel<<<(MDIM * (KDIM / 4)) / 256, 256>>>((const float4*)x);
    dequant_kernel<<<(NDIM * (KDIM / 2)) / 256, 256>>>(packed, d, dmin, scales, mins);
    gemm_tf32<<<dim3(NDIM / BN, MDIM / BM), 256, SMEM_BYTES>>>(out);
}

// round 16
// speedup vs baseline: 1.2767x; 1.2767x over previous
#include <cuda_runtime.h>
#include <cstdint>

// ---------------------------------------------------------------------------
// QuantLinear: y[M,N] = x[M,K] * W[N,K]^T, W dequantized from Q4_K-like format.
// M = 4096, K = 4096, N = 4096, fp32 in/out.
//
// Harness ptxas targets sm_103 (no 'a') -> no tcgen05. Use portable
// mma.sync m16n8k8 tf32 with unbiased RNA pre-rounding of both operands.
// R16: 3-stage pipeline (96KB smem) -> 2 CTAs/SM (16 warps), and ldmatrix.x4
// fragment loads (24 LDSM vs 96 LDS.32 per warp per K-tile).
// ---------------------------------------------------------------------------

static constexpr int MDIM = 4096;
static constexpr int NDIM = 4096;
static constexpr int KDIM = 4096;

static constexpr int BM = 128;
static constexpr int BN = 128;
static constexpr int BK = 32;
static constexpr int STAGES = 3;
static constexpr int KTILES = KDIM / BK;          // 128

static constexpr int TILE_FLOATS = BM * BK;       // 4096 floats = 16 KB
static constexpr int STAGE_FLOATS = 2 * TILE_FLOATS;
static constexpr int STAGE_BYTES = STAGE_FLOATS * 4;          // 32768
static constexpr int SMEM_BYTES = STAGES * STAGE_BYTES;       // 98304

// Scratch (device-global: no runtime allocation allowed)
__device__ float g_xr[(size_t)MDIM * KDIM];  // 64 MB tf32-rounded activations
__device__ float g_w [(size_t)NDIM * KDIM];  // 64 MB tf32-rounded weights [N][K]

// ---------------------------------------------------------------------------
// helpers
// ---------------------------------------------------------------------------
__device__ __forceinline__ float to_tf32(float v) {
    uint32_t t;
    asm("cvt.rna.tf32.f32 %0, %1;" : "=r"(t) : "f"(v));
    return __uint_as_float(t);
}

__device__ __forceinline__ uint32_t smem_u32(const void* p) {
    uint32_t a;
    asm("{ .reg .u64 t; cvta.to.shared.u64 t, %1; cvt.u32.u64 %0, t; }" : "=r"(a) : "l"(p));
    return a;
}

__device__ __forceinline__ void cp_async16(uint32_t smem_dst, const void* gmem_src) {
    asm volatile("cp.async.cg.shared.global [%0], [%1], 16;"
                 :: "r"(smem_dst), "l"(gmem_src) : "memory");
}

__device__ __forceinline__ void ldsm4(uint32_t* r, uint32_t addr) {
    asm volatile("ldmatrix.sync.aligned.m8n8.x4.shared.b16 {%0,%1,%2,%3}, [%4];"
                 : "=r"(r[0]), "=r"(r[1]), "=r"(r[2]), "=r"(r[3]) : "r"(addr));
}

__device__ __forceinline__ void mma_tf32(float* c, uint32_t a0, uint32_t a1,
                                         uint32_t a2, uint32_t a3,
                                         uint32_t b0, uint32_t b1) {
    asm volatile(
        "mma.sync.aligned.m16n8k8.row.col.f32.tf32.tf32.f32 "
        "{%0,%1,%2,%3}, {%4,%5,%6,%7}, {%8,%9}, {%0,%1,%2,%3};"
        : "+f"(c[0]), "+f"(c[1]), "+f"(c[2]), "+f"(c[3])
        : "r"(a0), "r"(a1), "r"(a2), "r"(a3), "r"(b0), "r"(b1));
}

// ---------------------------------------------------------------------------
// Kernel 1: round activations to tf32 (unbiased; removes truncation bias)
// ---------------------------------------------------------------------------
__global__ void __launch_bounds__(256) roundx_kernel(const float4* __restrict__ x) {
    int i = blockIdx.x * blockDim.x + threadIdx.x;
    float4 v = x[i];
    v.x = to_tf32(v.x); v.y = to_tf32(v.y); v.z = to_tf32(v.z); v.w = to_tf32(v.w);
    reinterpret_cast<float4*>(g_xr)[i] = v;
}

// ---------------------------------------------------------------------------
// Kernel 2: Q4_K dequantize -> g_w [N][K] row-major (K-major), tf32-rounded.
// ---------------------------------------------------------------------------
__global__ void __launch_bounds__(256) dequant_kernel(
    const int* __restrict__ packed, const float* __restrict__ d,
    const float* __restrict__ dmin, const int* __restrict__ scales,
    const int* __restrict__ mins) {
    int p = blockIdx.x * blockDim.x + threadIdx.x;   // 0 .. NUMEL/2-1
    int q = packed[p];
    int j = p << 1;
    int sup = j >> 8;
    int sbi = (sup << 3) + ((j >> 5) & 7);
    float sc = (float)scales[sbi] * (1.0f / 63.0f);
    float mn = (float)mins[sbi]   * (1.0f / 63.0f);
    float dd = d[sup];
    float dm = dmin[sup];
    float a = dd * sc * (1.0f / 15.0f);
    float b = mn * dd + dm;
    float w0 = (float)(q & 15)        * a + b;
    float w1 = (float)((q >> 4) & 15) * a + b;
    reinterpret_cast<float2*>(g_w)[p] = make_float2(to_tf32(w0), to_tf32(w1));
}

// ---------------------------------------------------------------------------
// Kernel 3: tf32 mma.sync GEMM, 128x128x32 CTA tile, 3-stage cp.async,
//   2 CTAs/SM, ldmatrix.x4 fragment loads, 8 warps (2Mx4N), warp tile 64x32.
// ---------------------------------------------------------------------------
__global__ void __launch_bounds__(256, 2) gemm_tf32(float* __restrict__ out) {
    extern __shared__ float smem[];
    const uint32_t sbase = smem_u32(smem);

    const int tid   = threadIdx.x;
    const int wid   = tid >> 5;
    const int lane  = tid & 31;
    const int group = lane >> 2;      // 0..7
    const int tid4  = lane & 3;       // 0..3
    const int warpM = wid >> 2;       // 0..1
    const int warpN = wid & 3;        // 0..3

    const int tile_m = blockIdx.y * BM;
    const int tile_n = blockIdx.x * BN;

    // ---- cp.async staging (proven layout: word = row*32 + (k ^ ((row&7)<<2)))
    const int lrow = tid >> 3;              // 0..31
    const int k4   = (tid & 7) << 2;        // 0,4,...,28
    const int swk  = k4 ^ ((lrow & 7) << 2);

    auto load_stage = [&](int slot, int kt) {
        const int kb = kt * BK;
        const uint32_t sA = sbase + (uint32_t)slot * STAGE_BYTES;
        const uint32_t sB = sA + (uint32_t)TILE_FLOATS * 4u;
        #pragma unroll
        for (int i = 0; i < 4; i++) {
            int row = lrow + i * 32;
            cp_async16(sA + (uint32_t)(row * BK + swk) * 4u,
                       &g_xr[(size_t)(tile_m + row) * KDIM + kb + k4]);
        }
        #pragma unroll
        for (int i = 0; i < 4; i++) {
            int row = lrow + i * 32;
            cp_async16(sB + (uint32_t)(row * BK + swk) * 4u,
                       &g_w[(size_t)(tile_n + row) * KDIM + kb + k4]);
        }
    };

    // ---- ldmatrix addressing (per-thread constants)
    const int r8  = lane & 7;               // row within 8-row block
    const int sub = lane >> 3;               // which of 4 matrices this thread feeds
    const int ssw = r8 << 2;                 // swizzle XOR for this thread's rows
    // A: matrices {0,1,2,3} = (rows +0, k+0), (rows +8, k+0), (rows +0, k+4), (rows +8, k+4)
    const int a_row = warpM * 64 + r8 + ((sub & 1) << 3);
    const int a_d   = (sub >> 1) << 2;
    // B: matrices {0,1,2,3} = (n +0, k+0), (n +0, k+4), (n +8, k+0), (n +8, k+4)
    const int b_row = warpN * 32 + r8 + ((sub >> 1) << 3);
    const int b_d   = (sub & 1) << 2;

    float accr[4][4][4];  // [mfrag][nfrag][reg]
    #pragma unroll
    for (int mf = 0; mf < 4; mf++)
        #pragma unroll
        for (int nf = 0; nf < 4; nf++)
            #pragma unroll
            for (int q = 0; q < 4; q++) accr[mf][nf][q] = 0.0f;

    // Prologue: fill STAGES-1 stages
    #pragma unroll
    for (int s = 0; s < STAGES - 1; s++) {
        load_stage(s, s);
        asm volatile("cp.async.commit_group;" ::: "memory");
    }

    int slot = 0;
    #pragma unroll 1
    for (int i = 0; i < KTILES; i++) {
        asm volatile("cp.async.wait_group %0;" :: "n"(STAGES - 2) : "memory");
        __syncthreads();

        // Prefetch into the slot freed at iteration i-1 (barrier above makes it safe)
        if (i + STAGES - 1 < KTILES) {
            int ps = slot + (STAGES - 1); if (ps >= STAGES) ps -= STAGES;
            load_stage(ps, i + STAGES - 1);
            asm volatile("cp.async.commit_group;" ::: "memory");
        }

        const uint32_t sA = sbase + (uint32_t)slot * STAGE_BYTES;
        const uint32_t sB = sA + (uint32_t)TILE_FLOATS * 4u;
        const uint32_t aBase = sA + (uint32_t)a_row * 128u;
        const uint32_t bBase = sB + (uint32_t)b_row * 128u;

        #pragma unroll
        for (int ks = 0; ks < BK / 8; ks++) {
            const uint32_t ka = (uint32_t)((((ks << 3) | a_d) ^ ssw) << 2);
            const uint32_t kb = (uint32_t)((((ks << 3) | b_d) ^ ssw) << 2);

            uint32_t a[4][4];
            #pragma unroll
            for (int mf = 0; mf < 4; mf++)
                ldsm4(a[mf], aBase + (uint32_t)(mf * 2048) + ka);

            uint32_t b[4][2];
            #pragma unroll
            for (int p = 0; p < 2; p++) {
                uint32_t bt[4];
                ldsm4(bt, bBase + (uint32_t)(p * 2048) + kb);
                b[2 * p][0] = bt[0];  b[2 * p][1] = bt[1];
                b[2 * p + 1][0] = bt[2];  b[2 * p + 1][1] = bt[3];
            }

            #pragma unroll
            for (int mf = 0; mf < 4; mf++)
                #pragma unroll
                for (int nf = 0; nf < 4; nf++)
                    mma_tf32(accr[mf][nf], a[mf][0], a[mf][1], a[mf][2], a[mf][3],
                             b[nf][0], b[nf][1]);
        }

        if (++slot == STAGES) slot = 0;
    }

    // Epilogue: direct fp32 stores (float2 per fragment half)
    #pragma unroll
    for (int mf = 0; mf < 4; mf++) {
        const int m0 = tile_m + warpM * 64 + mf * 16 + group;
        #pragma unroll
        for (int nf = 0; nf < 4; nf++) {
            const int n = tile_n + warpN * 32 + nf * 8 + tid4 * 2;
            float2 v0 = make_float2(accr[mf][nf][0], accr[mf][nf][1]);
            float2 v1 = make_float2(accr[mf][nf][2], accr[mf][nf][3]);
            *reinterpret_cast<float2*>(out + (size_t)m0 * NDIM + n) = v0;
            *reinterpret_cast<float2*>(out + (size_t)(m0 + 8) * NDIM + n) = v1;
        }
    }
}

// ---------------------------------------------------------------------------
// Launch
// ---------------------------------------------------------------------------
extern "C" void kernel_launch(void* const* d_in, const int* in_sizes, int n_in,
                              void* d_out, int out_size) {
    const float* x      = (const float*)d_in[0];
    const int*   packed = (const int*)  d_in[1];
    const float* d      = (const float*)d_in[2];
    const float* dmin   = (const float*)d_in[3];
    const int*   scales = (const int*)  d_in[4];
    const int*   mins   = (const int*)  d_in[5];
    float* out = (float*)d_out;

    cudaFuncSetAttribute(gemm_tf32, cudaFuncAttributeMaxDynamicSharedMemorySize,
                         SMEM_BYTES);

    roundx_kernel<<<(MDIM * (KDIM / 4)) / 256, 256>>>((const float4*)x);
    dequant_kernel<<<(NDIM * (KDIM / 2)) / 256, 256>>>(packed, d, dmin, scales, mins);
    gemm_tf32<<<dim3(NDIM / BN, MDIM / BM), 256, SMEM_BYTES>>>(out);
}

// round 17
// speedup vs baseline: 1.7122x; 1.3411x over previous
#include <cuda_runtime.h>
#include <cuda_fp16.h>
#include <cstdint>

// ---------------------------------------------------------------------------
// QuantLinear: y[M,N] = x[M,K] * W[N,K]^T, W dequantized from Q4_K-like format.
// M = 4096, K = 4096, N = 4096, fp32 in/out.
//
// Harness ptxas targets sm_103 (no 'a') -> no tcgen05. R17: fp16 operands
// (same 11-bit significand as tf32 -> same ~3e-4 rel_err) with m16n8k16 HMMA
// at 2x the tf32 rate, fp32 accumulation. 3-stage cp.async pipeline, BK=64,
// 2 CTAs/SM, ldmatrix.x4 fragment loads.
// ---------------------------------------------------------------------------

static constexpr int MDIM = 4096;
static constexpr int NDIM = 4096;
static constexpr int KDIM = 4096;

static constexpr int BM = 128;
static constexpr int BN = 128;
static constexpr int BK = 64;                      // fp16 elements (128 B rows)
static constexpr int STAGES = 3;
static constexpr int KTILES = KDIM / BK;           // 64

static constexpr int TILE_BYTES  = BM * BK * 2;    // 16384
static constexpr int STAGE_BYTES = 2 * TILE_BYTES; // 32768
static constexpr int SMEM_BYTES  = STAGES * STAGE_BYTES;  // 98304

// Scratch (device-global: no runtime allocation allowed)
__device__ __half g_xh[(size_t)MDIM * KDIM];  // 32 MB fp16 activations
__device__ __half g_wh[(size_t)NDIM * KDIM];  // 32 MB fp16 weights [N][K]

// ---------------------------------------------------------------------------
// helpers
// ---------------------------------------------------------------------------
__device__ __forceinline__ uint32_t smem_u32(const void* p) {
    uint32_t a;
    asm("{ .reg .u64 t; cvta.to.shared.u64 t, %1; cvt.u32.u64 %0, t; }" : "=r"(a) : "l"(p));
    return a;
}

__device__ __forceinline__ void cp_async16(uint32_t smem_dst, const void* gmem_src) {
    asm volatile("cp.async.cg.shared.global [%0], [%1], 16;"
                 :: "r"(smem_dst), "l"(gmem_src) : "memory");
}

__device__ __forceinline__ void ldsm4(uint32_t* r, uint32_t addr) {
    asm volatile("ldmatrix.sync.aligned.m8n8.x4.shared.b16 {%0,%1,%2,%3}, [%4];"
                 : "=r"(r[0]), "=r"(r[1]), "=r"(r[2]), "=r"(r[3]) : "r"(addr));
}

__device__ __forceinline__ void mma_f16(float* c, uint32_t a0, uint32_t a1,
                                        uint32_t a2, uint32_t a3,
                                        uint32_t b0, uint32_t b1) {
    asm volatile(
        "mma.sync.aligned.m16n8k16.row.col.f32.f16.f16.f32 "
        "{%0,%1,%2,%3}, {%4,%5,%6,%7}, {%8,%9}, {%0,%1,%2,%3};"
        : "+f"(c[0]), "+f"(c[1]), "+f"(c[2]), "+f"(c[3])
        : "r"(a0), "r"(a1), "r"(a2), "r"(a3), "r"(b0), "r"(b1));
}

// ---------------------------------------------------------------------------
// Kernel 1: convert activations fp32 -> fp16 (RNE)
// ---------------------------------------------------------------------------
__global__ void __launch_bounds__(256) convx_kernel(const float4* __restrict__ x) {
    int i = blockIdx.x * blockDim.x + threadIdx.x;   // 0 .. M*K/4-1
    float4 v = x[i];
    __half2 h0 = __floats2half2_rn(v.x, v.y);
    __half2 h1 = __floats2half2_rn(v.z, v.w);
    uint2 pk;
    pk.x = *reinterpret_cast<uint32_t*>(&h0);
    pk.y = *reinterpret_cast<uint32_t*>(&h1);
    reinterpret_cast<uint2*>(g_xh)[i] = pk;
}

// ---------------------------------------------------------------------------
// Kernel 2: Q4_K dequantize -> g_wh [N][K] (K-major), fp16.
//   j even -> low nibble of packed[j/2], j odd -> high nibble.
//   super = j>>8, sub = (j>>5)&7
//   w = (q/15 * scales/63 + mins/63) * d + dmin
// ---------------------------------------------------------------------------
__global__ void __launch_bounds__(256) dequant_kernel(
    const int* __restrict__ packed, const float* __restrict__ d,
    const float* __restrict__ dmin, const int* __restrict__ scales,
    const int* __restrict__ mins) {
    int p = blockIdx.x * blockDim.x + threadIdx.x;   // 0 .. NUMEL/2-1
    int q = packed[p];
    int j = p << 1;
    int sup = j >> 8;
    int sbi = (sup << 3) + ((j >> 5) & 7);
    float sc = (float)scales[sbi] * (1.0f / 63.0f);
    float mn = (float)mins[sbi]   * (1.0f / 63.0f);
    float dd = d[sup];
    float dm = dmin[sup];
    float a = dd * sc * (1.0f / 15.0f);
    float b = mn * dd + dm;
    float w0 = (float)(q & 15)        * a + b;
    float w1 = (float)((q >> 4) & 15) * a + b;
    __half2 h = __floats2half2_rn(w0, w1);
    reinterpret_cast<__half2*>(g_wh)[p] = h;
}

// ---------------------------------------------------------------------------
// Kernel 3: fp16 mma.sync GEMM. CTA 128x128x64, 3-stage cp.async, 2 CTAs/SM,
//   8 warps (2M x 4N), warp tile 64x32, m16n8k16, fp32 accumulators.
//   SMEM rows: 128 B (64 fp16), chunk swizzle: chunk' = chunk ^ (row & 7).
// ---------------------------------------------------------------------------
__global__ void __launch_bounds__(256, 2) gemm_f16(float* __restrict__ out) {
    extern __shared__ char smem[];
    const uint32_t sbase = smem_u32(smem);

    const int tid   = threadIdx.x;
    const int wid   = tid >> 5;
    const int lane  = tid & 31;
    const int group = lane >> 2;      // 0..7
    const int tid4  = lane & 3;       // 0..3
    const int warpM = wid >> 2;       // 0..1
    const int warpN = wid & 3;        // 0..3

    const int tile_m = blockIdx.y * BM;
    const int tile_n = blockIdx.x * BN;

    // ---- cp.async staging: 128 rows x 8 chunks(16B) per tile, 256 threads
    //      thread t: row = t>>1, chunks (t&1)*4 .. +3
    const int srow  = tid >> 1;             // 0..127
    const int cbase = (tid & 1) << 2;       // 0 or 4
    const int rsw   = srow & 7;

    auto load_stage = [&](int slot, int kt) {
        const int kb = kt * BK;                       // fp16 index
        const uint32_t sA = sbase + (uint32_t)slot * STAGE_BYTES;
        const uint32_t sB = sA + (uint32_t)TILE_BYTES;
        const __half* gA = &g_xh[(size_t)(tile_m + srow) * KDIM + kb];
        const __half* gB = &g_wh[(size_t)(tile_n + srow) * KDIM + kb];
        const uint32_t rowA = sA + (uint32_t)srow * 128u;
        const uint32_t rowB = sB + (uint32_t)srow * 128u;
        #pragma unroll
        for (int c = 0; c < 4; c++) {
            int ch = cbase + c;
            cp_async16(rowA + (uint32_t)((ch ^ rsw) << 4), gA + ch * 8);
        }
        #pragma unroll
        for (int c = 0; c < 4; c++) {
            int ch = cbase + c;
            cp_async16(rowB + (uint32_t)((ch ^ rsw) << 4), gB + ch * 8);
        }
    };

    // ---- ldmatrix addressing (per-thread constants)
    const int r8  = lane & 7;                // row within 8-row block
    const int sub = lane >> 3;               // matrix index 0..3
    // A x4: m0=(rows+0,k+0) m1=(rows+8,k+0) m2=(rows+0,k+8) m3=(rows+8,k+8)
    const int a_row = warpM * 64 + r8 + ((sub & 1) << 3);
    const int a_kc  = (sub >> 1);            // k-chunk offset 0/1 (8 fp16 each)
    // B x4: m0=(n+0,k+0) m1=(n+0,k+8) m2=(n+8,k+0) m3=(n+8,k+8)
    const int b_row = warpN * 32 + r8 + ((sub >> 1) << 3);
    const int b_kc  = (sub & 1);

    float accr[4][4][4];  // [mfrag][nfrag][reg]
    #pragma unroll
    for (int mf = 0; mf < 4; mf++)
        #pragma unroll
        for (int nf = 0; nf < 4; nf++)
            #pragma unroll
            for (int q = 0; q < 4; q++) accr[mf][nf][q] = 0.0f;

    // Prologue
    #pragma unroll
    for (int s = 0; s < STAGES - 1; s++) {
        load_stage(s, s);
        asm volatile("cp.async.commit_group;" ::: "memory");
    }

    int slot = 0;
    #pragma unroll 1
    for (int i = 0; i < KTILES; i++) {
        asm volatile("cp.async.wait_group %0;" :: "n"(STAGES - 2) : "memory");
        __syncthreads();

        if (i + STAGES - 1 < KTILES) {
            int ps = slot + (STAGES - 1); if (ps >= STAGES) ps -= STAGES;
            load_stage(ps, i + STAGES - 1);
            asm volatile("cp.async.commit_group;" ::: "memory");
        }

        const uint32_t sA = sbase + (uint32_t)slot * STAGE_BYTES;
        const uint32_t sB = sA + (uint32_t)TILE_BYTES;
        const uint32_t aBase = sA + (uint32_t)a_row * 128u;
        const uint32_t bBase = sB + (uint32_t)b_row * 128u;
        const int aswz = a_row & 7;
        const int bswz = b_row & 7;

        #pragma unroll
        for (int ks = 0; ks < BK / 16; ks++) {       // 4 k16 steps
            const uint32_t ka = (uint32_t)((((ks << 1) | a_kc) ^ aswz) << 4);
            const uint32_t kb = (uint32_t)((((ks << 1) | b_kc) ^ bswz) << 4);

            uint32_t a[4][4];
            #pragma unroll
            for (int mf = 0; mf < 4; mf++)
                ldsm4(a[mf], aBase + (uint32_t)(mf * 2048) + ka);

            uint32_t b[4][2];
            #pragma unroll
            for (int p = 0; p < 2; p++) {            // npair covers nf 2p, 2p+1
                uint32_t bt[4];
                ldsm4(bt, bBase + (uint32_t)(p * 2048) + kb);
                b[2 * p][0]     = bt[0];  b[2 * p][1]     = bt[1];
                b[2 * p + 1][0] = bt[2];  b[2 * p + 1][1] = bt[3];
            }

            #pragma unroll
            for (int mf = 0; mf < 4; mf++)
                #pragma unroll
                for (int nf = 0; nf < 4; nf++)
                    mma_f16(accr[mf][nf], a[mf][0], a[mf][1], a[mf][2], a[mf][3],
                            b[nf][0], b[nf][1]);
        }

        if (++slot == STAGES) slot = 0;
    }

    // Epilogue: direct fp32 stores (float2 per fragment half)
    #pragma unroll
    for (int mf = 0; mf < 4; mf++) {
        const int m0 = tile_m + warpM * 64 + mf * 16 + group;
        #pragma unroll
        for (int nf = 0; nf < 4; nf++) {
            const int n = tile_n + warpN * 32 + nf * 8 + tid4 * 2;
            float2 v0 = make_float2(accr[mf][nf][0], accr[mf][nf][1]);
            float2 v1 = make_float2(accr[mf][nf][2], accr[mf][nf][3]);
            *reinterpret_cast<float2*>(out + (size_t)m0 * NDIM + n) = v0;
            *reinterpret_cast<float2*>(out + (size_t)(m0 + 8) * NDIM + n) = v1;
        }
    }
}

// ---------------------------------------------------------------------------
// Launch
// ---------------------------------------------------------------------------
extern "C" void kernel_launch(void* const* d_in, const int* in_sizes, int n_in,
                              void* d_out, int out_size) {
    const float* x      = (const float*)d_in[0];
    const int*   packed = (const int*)  d_in[1];
    const float* d      = (const float*)d_in[2];
    const float* dmin   = (const float*)d_in[3];
    const int*   scales = (const int*)  d_in[4];
    const int*   mins   = (const int*)  d_in[5];
    float* out = (float*)d_out;

    cudaFuncSetAttribute(gemm_f16, cudaFuncAttributeMaxDynamicSharedMemorySize,
                         SMEM_BYTES);

    convx_kernel<<<(MDIM * (KDIM / 4)) / 256, 256>>>((const float4*)x);
    dequant_kernel<<<(NDIM * (KDIM / 2)) / 256, 256>>>(packed, d, dmin, scales, mins);
    gemm_f16<<<dim3(NDIM / BN, MDIM / BM), 256, SMEM_BYTES>>>(out);
}